// round 16
// baseline (speedup 1.0000x reference)
#include <cuda_runtime.h>
#include <cuda_bf16.h>

// Resample2d bilinear warp — direct scalar gather, ONE-WAVE grid-stride
// over R14 tiles (static work smoothing, no atomics).
// input1: [8,64,384,512] f32, input2(flow): [8,2,384,512] f32, out NCHW f32.
//
// R2-R15: divergent-gather l1tex wavefronts are the structural floor; DCH=16
// channel-split + __stcs (R14, 207.6us) is the best static schedule. L1 util
// 87.9% -> remaining slack is cross-SM tail/spread. This round: launch
// exactly one wave (1184 blocks = 148 SMs x 8) and grid-stride each block
// over the 24576 tiles (~21 tiles/block). Per-block duration averages 21
// tile durations (CLT: spread /~4.6) and multi-wave transitions vanish.
// Inner tile work identical to R14.

#define B_ 8
#define D_ 64
#define H_ 384
#define W_ 512
#define PLANE_ (H_ * W_)
#define TPB 256
#define DCH 16                  // channels per tile
#define DSPLIT (D_ / DCH)       // 4
#define NTILES (B_ * H_ * (W_ / TPB) * DSPLIT)   // 24576
#define NBLK 1184               // 148 SMs * 8 resident blocks (32 regs, 256 thr)

__global__ __launch_bounds__(TPB)
void resample2d_kernel(const float* __restrict__ img,
                       const float* __restrict__ flow,
                       float* __restrict__ out)
{
    for (int t = blockIdx.x; t < NTILES; t += NBLK) {
        // t = ((b*H + h)*WCHUNKS + wc)*DSPLIT + ds   (R14 decode)
        int bid = t;
        const int ds = bid & (DSPLIT - 1);
        bid >>= 2;
        const int wc = bid & 1;                  // W/TPB = 2
        bid >>= 1;
        const int h = bid % H_;
        const int b = bid / H_;
        const int w = wc * TPB + threadIdx.x;
        const int d0 = ds * DCH;

        // flow [B,2,H,W]
        const unsigned foff = (unsigned)b * (2u * PLANE_) + (unsigned)h * W_ + w;
        const float u = __ldg(flow + foff);
        const float v = __ldg(flow + foff + PLANE_);

        float fx = (float)w + u;
        float fy = (float)h + v;
        fx = fminf(fmaxf(fx, 0.0f), (float)(W_ - 1));
        fy = fminf(fmaxf(fy, 0.0f), (float)(H_ - 1));
        const int x0 = min((int)fx, W_ - 2);
        const int y0 = min((int)fy, H_ - 2);
        const float wx = fx - (float)x0;
        const float wy = fy - (float)y0;

        const float w00 = (1.0f - wy) * (1.0f - wx);
        const float w01 = (1.0f - wy) * wx;
        const float w10 = wy * (1.0f - wx);
        const float w11 = wy * wx;

        // 32-bit element offsets (tensor = 100.6M elems < 2^31)
        unsigned o0 = (unsigned)b * (D_ * PLANE_) + (unsigned)d0 * PLANE_
                    + (unsigned)y0 * W_ + (unsigned)x0;
        unsigned o1 = o0 + W_;
        unsigned oo = (unsigned)b * (D_ * PLANE_) + (unsigned)d0 * PLANE_
                    + (unsigned)h * W_ + (unsigned)w;

        #pragma unroll
        for (int d = 0; d < DCH; ++d) {
            const float a00 = __ldg(img + o0);
            const float a01 = __ldg(img + o0 + 1);
            const float a10 = __ldg(img + o1);
            const float a11 = __ldg(img + o1 + 1);
            float r = w00 * a00;
            r = fmaf(w01, a01, r);
            r = fmaf(w10, a10, r);
            r = fmaf(w11, a11, r);
            __stcs(out + oo, r);
            o0 += PLANE_;
            o1 += PLANE_;
            oo += PLANE_;
        }
    }
}

extern "C" void kernel_launch(void* const* d_in, const int* in_sizes, int n_in,
                              void* d_out, int out_size)
{
    const float* img  = (const float*)d_in[0];
    const float* flow = (const float*)d_in[1];
    float* out = (float*)d_out;

    dim3 grid(NBLK);
    dim3 block(TPB);
    resample2d_kernel<<<grid, block>>>(img, flow, out);
}

// round 17
// speedup vs baseline: 1.1965x; 1.1965x over previous
#include <cuda_runtime.h>
#include <cuda_bf16.h>

// Resample2d bilinear warp — direct scalar gather, DCH=16 channel split,
// TPB=128 for finer HW scheduling granularity.
// input1: [8,64,384,512] f32, input2(flow): [8,2,384,512] f32, out NCHW f32.
//
// Converged family (R2-R16): divergent-gather l1tex wavefronts are the
// structural floor; best schedule = many short blocks balanced by the HW
// work distributor (R14: DCH=16 + __stcs, 207.6us; grid-stride R16 regressed
// to 250us -> long-lived blocks expose tile-boundary latency). This round
// halves block size (128 thr) at unchanged DCH=16: same per-warp gather
// footprint, same flow-reread count, 2x finer scheduling granules.

#define B_ 8
#define D_ 64
#define H_ 384
#define W_ 512
#define PLANE_ (H_ * W_)
#define TPB 128
#define WCHUNKS (W_ / TPB)     // 4
#define DCH 16                 // channels per block
#define DSPLIT (D_ / DCH)      // 4

__global__ __launch_bounds__(TPB)
void resample2d_kernel(const float* __restrict__ img,
                       const float* __restrict__ flow,
                       float* __restrict__ out)
{
    // blockIdx.x = ((b*H + h)*WCHUNKS + wc)*DSPLIT + ds
    int bid = blockIdx.x;
    const int ds = bid & (DSPLIT - 1);
    bid >>= 2;
    const int wc = bid & (WCHUNKS - 1);
    bid >>= 2;
    const int h = bid % H_;
    const int b = bid / H_;
    const int w = wc * TPB + threadIdx.x;
    const int d0 = ds * DCH;

    // flow [B,2,H,W]
    const unsigned foff = (unsigned)b * (2u * PLANE_) + (unsigned)h * W_ + w;
    const float u = __ldg(flow + foff);
    const float v = __ldg(flow + foff + PLANE_);

    float fx = (float)w + u;
    float fy = (float)h + v;
    fx = fminf(fmaxf(fx, 0.0f), (float)(W_ - 1));
    fy = fminf(fmaxf(fy, 0.0f), (float)(H_ - 1));
    const int x0 = min((int)fx, W_ - 2);
    const int y0 = min((int)fy, H_ - 2);
    const float wx = fx - (float)x0;
    const float wy = fy - (float)y0;

    const float w00 = (1.0f - wy) * (1.0f - wx);
    const float w01 = (1.0f - wy) * wx;
    const float w10 = wy * (1.0f - wx);
    const float w11 = wy * wx;

    // 32-bit element offsets (tensor = 100.6M elems < 2^31)
    unsigned o0 = (unsigned)b * (D_ * PLANE_) + (unsigned)d0 * PLANE_
                + (unsigned)y0 * W_ + (unsigned)x0;
    unsigned o1 = o0 + W_;
    unsigned oo = (unsigned)b * (D_ * PLANE_) + (unsigned)d0 * PLANE_
                + (unsigned)h * W_ + (unsigned)w;

    #pragma unroll
    for (int d = 0; d < DCH; ++d) {
        const float a00 = __ldg(img + o0);
        const float a01 = __ldg(img + o0 + 1);
        const float a10 = __ldg(img + o1);
        const float a11 = __ldg(img + o1 + 1);
        float r = w00 * a00;
        r = fmaf(w01, a01, r);
        r = fmaf(w10, a10, r);
        r = fmaf(w11, a11, r);
        __stcs(out + oo, r);
        o0 += PLANE_;
        o1 += PLANE_;
        oo += PLANE_;
    }
}

extern "C" void kernel_launch(void* const* d_in, const int* in_sizes, int n_in,
                              void* d_out, int out_size)
{
    const float* img  = (const float*)d_in[0];
    const float* flow = (const float*)d_in[1];
    float* out = (float*)d_out;

    dim3 grid(B_ * H_ * WCHUNKS * DSPLIT);   // 8*384*4*4 = 49152
    dim3 block(TPB);
    resample2d_kernel<<<grid, block>>>(img, flow, out);
}